// round 15
// baseline (speedup 1.0000x reference)
#include <cuda_runtime.h>
#include <cuda_bf16.h>
#include <cuda_fp16.h>
#include <math.h>
#include <stdint.h>

// Problem constants
#define Bq 4
#define Sq 8192
#define Dq 512
#define Hq 8
#define HDq 64
#define Mq (Bq * Sq)           // 32768
#define Nqkv (3 * Dq)          // 1536

// ---------------- scratch (static device memory; no allocations) ----------------
__device__ float g_q[(size_t)Mq * Dq];
__device__ float g_k[(size_t)Mq * Dq];
__device__ float g_v[(size_t)Mq * Dq];
__device__ float g_kv[Bq * Hq * HDq * HDq];
__device__ float g_ksum[Bq * Hq * HDq];
__device__ float g_mask[Mq];
// fp16 split operands: A = ah + al (2-term), B = bh only
__device__ __half g_ah[(size_t)Mq * Dq];     // query hi
__device__ __half g_al[(size_t)Mq * Dq];     // query lo
__device__ __half g_oh[(size_t)Mq * Dq];     // attn out hi
__device__ __half g_ol[(size_t)Mq * Dq];     // attn out lo
__device__ __half g_wih[(size_t)Nqkv * Dq];  // in_proj W (fp16)
__device__ __half g_woh[(size_t)Dq * Dq];    // out_proj W (fp16)

__device__ __forceinline__ uint32_t smem_u32(const void* p) {
    uint32_t a;
    asm("{ .reg .u64 t; cvta.to.shared.u64 t, %1; cvt.u32.u64 %0, t; }" : "=r"(a) : "l"(p));
    return a;
}

#define CP_ASYNC16(dst, src) \
    asm volatile("cp.async.cg.shared.global [%0], [%1], 16;" :: "r"(dst), "l"(src))
#define CP_COMMIT() asm volatile("cp.async.commit_group;" ::: "memory")
#define CP_WAIT(N)  asm volatile("cp.async.wait_group %0;" :: "n"(N) : "memory")

__device__ __forceinline__ float phi(float x) { return x > 0.0f ? x + 1.0f : expf(x); }

__device__ __forceinline__ uint32_t pack2h(__half a, __half b) {
    __half2 p; p.x = a; p.y = b;
    return *reinterpret_cast<uint32_t*>(&p);
}

// ---------------- fused setup: mask canonicalization + kv zero + fp16 splits ----------------
#define N4_Q   ((Mq * (size_t)Dq) / 4)
#define N4_WI  ((Nqkv * (size_t)Dq) / 4)
#define N4_WO  ((Dq * (size_t)Dq) / 4)
__global__ void setup_kernel(const void* __restrict__ mraw, const float* __restrict__ q,
                             const float* __restrict__ wi, const float* __restrict__ wo) {
    const size_t gtid = blockIdx.x * (size_t)blockDim.x + threadIdx.x;
    const size_t gstride = gridDim.x * (size_t)blockDim.x;

    if (blockIdx.x == 0) {
        __shared__ int s_f32, s_big;
        if (threadIdx.x == 0) { s_f32 = 0; s_big = 0; }
        __syncthreads();
        const unsigned int* w = (const unsigned int*)mraw;
        int f32 = 0, big = 0;
        for (int i = threadIdx.x; i < 8192; i += blockDim.x) {
            unsigned int x = w[i];
            if (x == 0x3F800000u) f32 = 1;
            else if (x > 1u) big = 1;
        }
        if (f32) atomicOr(&s_f32, 1);
        if (big) atomicOr(&s_big, 1);
        __syncthreads();
        int mode = s_f32 ? 2 : (s_big ? 0 : 1);
        for (int i = threadIdx.x; i < Mq; i += blockDim.x) {
            bool pad;
            if (mode == 0)      pad = ((const unsigned char*)mraw)[i] != 0;
            else if (mode == 1) pad = ((const int*)mraw)[i] != 0;
            else                pad = ((const float*)mraw)[i] != 0.0f;
            g_mask[i] = pad ? 0.0f : 1.0f;
        }
    }
    for (size_t i = gtid; i < Bq * Hq * HDq * HDq; i += gstride) g_kv[i] = 0.0f;
    for (size_t i = gtid; i < Bq * Hq * HDq; i += gstride) g_ksum[i] = 0.0f;

    const size_t total = N4_Q + N4_WI + N4_WO;
    for (size_t i = gtid; i < total; i += gstride) {
        const float* src; __half *dh, *dl; size_t j; bool wantlo;
        if (i < N4_Q)              { src = q;  dh = g_ah;  dl = g_al; j = i; wantlo = true; }
        else if (i < N4_Q + N4_WI) { src = wi; dh = g_wih; dl = 0; j = i - N4_Q; wantlo = false; }
        else                       { src = wo; dh = g_woh; dl = 0; j = i - N4_Q - N4_WI; wantlo = false; }
        float4 v = ((const float4*)src)[j];
        __half h0 = __float2half_rn(v.x), h1 = __float2half_rn(v.y);
        __half h2 = __float2half_rn(v.z), h3 = __float2half_rn(v.w);
        ((uint2*)dh)[j] = make_uint2(pack2h(h0, h1), pack2h(h2, h3));
        if (wantlo) {
            __half l0 = __float2half_rn(v.x - __half2float(h0));
            __half l1 = __float2half_rn(v.y - __half2float(h1));
            __half l2 = __float2half_rn(v.z - __half2float(h2));
            __half l3 = __float2half_rn(v.w - __half2float(h3));
            ((uint2*)dl)[j] = make_uint2(pack2h(l0, l1), pack2h(l2, l3));
        }
    }
}

#define LDM_X4(r0, r1, r2, r3, addr) \
    asm volatile("ldmatrix.sync.aligned.m8n8.x4.shared.b16 {%0,%1,%2,%3}, [%4];" \
                 : "=r"(r0), "=r"(r1), "=r"(r2), "=r"(r3) : "r"(addr))

__device__ __forceinline__ void mma_fp16(float* c, const uint32_t* a, uint32_t b0, uint32_t b1) {
    asm volatile(
        "mma.sync.aligned.m16n8k16.row.col.f32.f16.f16.f32 "
        "{%0,%1,%2,%3}, {%4,%5,%6,%7}, {%8,%9}, {%0,%1,%2,%3};"
        : "+f"(c[0]), "+f"(c[1]), "+f"(c[2]), "+f"(c[3])
        : "r"(a[0]), "r"(a[1]), "r"(a[2]), "r"(a[3]), "r"(b0), "r"(b1));
}

// ---------------- tensor-core GEMM, 64x128 CTA tile, 4 CTAs/SM ----------------
// 128 threads, 4 warps (1x4), warp tile 64x32 (per-warp code unchanged), K-chunk 32,
// 2-stage double buffer, fp16 2-product. Four independent barrier domains per SM:
// each __syncthreads stalls only 4 warps while 12 others issue.
#define STG_STRIDE 48
#define A_TILE_B  3072                  // 64 rows * 48B
#define B_TILE_B  6144                  // 128 rows * 48B
#define OFF_AL    A_TILE_B
#define OFF_BH    (2 * A_TILE_B)
#define SUB_B     (2 * A_TILE_B + B_TILE_B)   // Ah Al Bh = 12288
#define STAGE_B   (2 * SUB_B)           // 32-K chunk = 24576
#define GEMM_SMEM (2 * STAGE_B)         // 49152 per CTA -> 4 CTAs/SM
#define NCHUNK 16                       // K=512 / 32

__global__ __launch_bounds__(128, 4)
void tc_gemm(const float* __restrict__ bias, float* __restrict__ Cout, int mode) {
    extern __shared__ __align__(128) unsigned char smbuf[];

    const __half *Ah, *Al, *Bh;
    if (mode == 0) { Ah = g_ah; Al = g_al; Bh = g_wih; }
    else           { Ah = g_oh; Al = g_ol; Bh = g_woh; }

    const int tid = threadIdx.x;
    const int lane = tid & 31, warp = tid >> 5;
    const int wc = warp;                             // 1x4 warp grid; 64x32 tiles
    const int m0 = blockIdx.y * 64, n0 = blockIdx.x * 128;
    const uint32_t sb = smem_u32(smbuf);

    // loaders: A = 64 rows, 2 threads/row (hi+lo 16B each);
    //          B = 128 rows, 1 thread/row (both 16B halves).
    const int arow = tid >> 1;                       // 0..63
    const int half = tid & 1;
    const __half* srcAh = Ah + (size_t)(m0 + arow) * Dq + half * 8;
    const __half* srcAl = Al + (size_t)(m0 + arow) * Dq + half * 8;
    const uint32_t dstA = sb + (uint32_t)(arow * STG_STRIDE + half * 16);
    const __half* srcBh = Bh + (size_t)(n0 + tid) * Dq;
    const uint32_t dstB = sb + (uint32_t)(OFF_BH + tid * STG_STRIDE);

    const int quad = lane >> 3, lrow = lane & 7;
    const uint32_t rowoff = (uint32_t)(((quad & 1) * 8 + lrow) * STG_STRIDE + (quad >> 1) * 16);

    float acc[4][4][4];
#pragma unroll
    for (int i = 0; i < 4; i++)
#pragma unroll
        for (int j = 0; j < 4; j++)
#pragma unroll
            for (int r = 0; r < 4; r++) acc[i][j][r] = 0.0f;

    // prologue: issue chunk 0 (two 16-K sub-tiles)
#pragma unroll
    for (int s = 0; s < 2; s++) {
        uint32_t so = (uint32_t)(s * SUB_B);
        CP_ASYNC16(dstA + so, srcAh + s * 16);
        CP_ASYNC16(dstA + so + OFF_AL, srcAl + s * 16);
        CP_ASYNC16(dstB + so, srcBh + s * 16);
        CP_ASYNC16(dstB + so + 16, srcBh + s * 16 + 8);
    }
    CP_COMMIT();

#pragma unroll 2
    for (int c = 0; c < NCHUNK; c++) {
        if (c < NCHUNK - 1) {
            uint32_t ds = (uint32_t)(((c + 1) & 1) * STAGE_B);
#pragma unroll
            for (int s = 0; s < 2; s++) {
                uint32_t so = ds + (uint32_t)(s * SUB_B);
                int ko = (c + 1) * 32 + s * 16;
                CP_ASYNC16(dstA + so, srcAh + ko);
                CP_ASYNC16(dstA + so + OFF_AL, srcAl + ko);
                CP_ASYNC16(dstB + so, srcBh + ko);
                CP_ASYNC16(dstB + so + 16, srcBh + ko + 8);
            }
            CP_COMMIT();
            CP_WAIT(1);
        } else {
            CP_WAIT(0);
        }
        __syncthreads();

#pragma unroll
        for (int s = 0; s < 2; s++) {
            uint32_t stage = sb + (uint32_t)((c & 1) * STAGE_B) + (uint32_t)(s * SUB_B);
            uint32_t bh[2][4];
#pragma unroll
            for (int np = 0; np < 2; np++) {
                uint32_t baddr = stage + OFF_BH +
                                 (uint32_t)((wc * 32 + np * 16) * STG_STRIDE) + rowoff;
                LDM_X4(bh[np][0], bh[np][1], bh[np][2], bh[np][3], baddr);
            }
            uint32_t ah[4][4];
#pragma unroll
            for (int mf = 0; mf < 4; mf++) {
                uint32_t aaddr = stage + (uint32_t)((mf * 16) * STG_STRIDE) + rowoff;
                LDM_X4(ah[mf][0], ah[mf][1], ah[mf][2], ah[mf][3], aaddr);
            }
            // P1: ah*bh
#pragma unroll
            for (int mf = 0; mf < 4; mf++)
#pragma unroll
                for (int nf = 0; nf < 4; nf++) {
                    int np = nf >> 1, od = nf & 1;
                    mma_fp16(acc[mf][nf], ah[mf], bh[np][od], bh[np][od + 2]);
                }
            uint32_t al[4][4];
#pragma unroll
            for (int mf = 0; mf < 4; mf++) {
                uint32_t aaddr = stage + OFF_AL + (uint32_t)((mf * 16) * STG_STRIDE) + rowoff;
                LDM_X4(al[mf][0], al[mf][1], al[mf][2], al[mf][3], aaddr);
            }
            // P2: al*bh
#pragma unroll
            for (int mf = 0; mf < 4; mf++)
#pragma unroll
                for (int nf = 0; nf < 4; nf++) {
                    int np = nf >> 1, od = nf & 1;
                    mma_fp16(acc[mf][nf], al[mf], bh[np][od], bh[np][od + 2]);
                }
        }
        __syncthreads();
    }

    // ---------------- epilogue ----------------
    int region = n0 >> 9;
    int nc0 = n0 & 511;
    float* dst = (mode == 1) ? Cout : (region == 0 ? g_q : (region == 1 ? g_k : g_v));

#pragma unroll
    for (int mf = 0; mf < 4; mf++) {
#pragma unroll
        for (int pr = 0; pr < 2; pr++) {
            int r = m0 + mf * 16 + (lane >> 2) + pr * 8;
            float mv = (mode == 0) ? g_mask[r] : 0.0f;
#pragma unroll
            for (int nf = 0; nf < 4; nf++) {
                int col = wc * 32 + nf * 8 + (lane & 3) * 2;
                float2 bs = *(const float2*)(bias + n0 + col);
                float v0 = acc[mf][nf][pr * 2 + 0] + bs.x;
                float v1 = acc[mf][nf][pr * 2 + 1] + bs.y;
                if (mode == 0) {
                    if (region == 0)      { v0 = phi(v0);       v1 = phi(v1); }
                    else if (region == 1) { v0 = phi(v0) * mv;  v1 = phi(v1) * mv; }
                    else                  { v0 = v0 * mv;       v1 = v1 * mv; }
                    *(float2*)(dst + (size_t)r * Dq + nc0 + col) = make_float2(v0, v1);
                } else {
                    *(float2*)(dst + (size_t)r * Dq + n0 + col) = make_float2(v0, v1);
                }
            }
        }
    }
}

// ---------------- kv[bh][d][e] = sum_s k[s][d]*v[s][e]; ksum[bh][d] = sum_s k[s][d] ----------------
#define KV_CHUNKS 32
__global__ __launch_bounds__(256)
void kv_kernel() {
    const int bh = blockIdx.x;
    const int chunk = blockIdx.y;
    const int b = bh >> 3, h = bh & 7;
    const int CH = Sq / KV_CHUNKS;          // 256
    const int s_base = chunk * CH;
    const size_t tokbase = (size_t)b * Sq;

    __shared__ float ks[32][64];
    __shared__ float vs[32][64];

    const int tid = threadIdx.x;
    const int d0 = (tid >> 4) * 4;
    const int e0 = (tid & 15) * 4;
    const int lrow = tid >> 3;
    const int lcol = (tid & 7) * 8;

    float acc[4][4];
#pragma unroll
    for (int i = 0; i < 4; i++)
#pragma unroll
        for (int j = 0; j < 4; j++) acc[i][j] = 0.0f;
    float ksum[4] = {0.f, 0.f, 0.f, 0.f};

    for (int st = 0; st < CH; st += 32) {
        size_t gb = (tokbase + s_base + st + lrow) * Dq + h * HDq + lcol;
        float4 k1 = *(const float4*)(g_k + gb);
        float4 k2 = *(const float4*)(g_k + gb + 4);
        float4 v1 = *(const float4*)(g_v + gb);
        float4 v2 = *(const float4*)(g_v + gb + 4);
        *(float4*)&ks[lrow][lcol]     = k1;
        *(float4*)&ks[lrow][lcol + 4] = k2;
        *(float4*)&vs[lrow][lcol]     = v1;
        *(float4*)&vs[lrow][lcol + 4] = v2;
        __syncthreads();
#pragma unroll 8
        for (int s = 0; s < 32; s++) {
            float4 kd = *(const float4*)&ks[s][d0];
            float4 ve = *(const float4*)&vs[s][e0];
            float kdv[4] = {kd.x, kd.y, kd.z, kd.w};
            float vev[4] = {ve.x, ve.y, ve.z, ve.w};
#pragma unroll
            for (int i = 0; i < 4; i++)
#pragma unroll
                for (int j = 0; j < 4; j++) acc[i][j] = fmaf(kdv[i], vev[j], acc[i][j]);
            if (e0 == 0) {
#pragma unroll
                for (int i = 0; i < 4; i++) ksum[i] += kdv[i];
            }
        }
        __syncthreads();
    }

    float* kvp = g_kv + bh * (HDq * HDq);
#pragma unroll
    for (int i = 0; i < 4; i++)
#pragma unroll
        for (int j = 0; j < 4; j++)
            atomicAdd(&kvp[(d0 + i) * HDq + (e0 + j)], acc[i][j]);
    if (e0 == 0) {
#pragma unroll
        for (int i = 0; i < 4; i++) atomicAdd(&g_ksum[bh * HDq + d0 + i], ksum[i]);
    }
}

// ---------------- attn (R12-proven): 128-token tiles, 512 threads ----------------
__global__ __launch_bounds__(512)
void attn_kernel() {
    const int bh = blockIdx.x;
    const int tile = blockIdx.y;
    const int b = bh >> 3, h = bh & 7;
    const int s0 = tile * 128;

    __shared__ float kvs[64][64];
    __shared__ float qs[128][64];
    __shared__ float ksm[64];
    __shared__ float dens[128];

    const int tid = threadIdx.x;

    {
        const float4* src = (const float4*)(g_kv + bh * (HDq * HDq));
        float4* dst = (float4*)&kvs[0][0];
        for (int i = tid; i < 1024; i += 512) dst[i] = src[i];
    }
    if (tid < 64) ksm[tid] = g_ksum[bh * HDq + tid];
    {
        int t = tid >> 2;
        int off = (tid & 3) * 16;
        const float4* src = (const float4*)(g_q + ((size_t)(b * Sq + s0 + t)) * Dq + h * HDq + off);
        float4* dst = (float4*)&qs[t][off];
#pragma unroll
        for (int u = 0; u < 4; u++) dst[u] = src[u];
    }
    __syncthreads();

    const int t0 = (tid >> 4) * 4;
    const int e0 = (tid & 15) * 4;
    float acc[4][4];
#pragma unroll
    for (int i = 0; i < 4; i++)
#pragma unroll
        for (int j = 0; j < 4; j++) acc[i][j] = 0.0f;
    float den[4] = {0.f, 0.f, 0.f, 0.f};

#pragma unroll 8
    for (int d = 0; d < 64; d++) {
        float4 kv4 = *(const float4*)&kvs[d][e0];
        float kvv[4] = {kv4.x, kv4.y, kv4.z, kv4.w};
        float kc = ksm[d];
#pragma unroll
        for (int tt = 0; tt < 4; tt++) {
            float qv = qs[t0 + tt][d];
#pragma unroll
            for (int j = 0; j < 4; j++) acc[tt][j] = fmaf(qv, kvv[j], acc[tt][j]);
            if (e0 == 0) den[tt] = fmaf(qv, kc, den[tt]);
        }
    }
    if (e0 == 0) {
#pragma unroll
        for (int tt = 0; tt < 4; tt++) dens[t0 + tt] = den[tt];
    }
    __syncthreads();

#pragma unroll
    for (int tt = 0; tt < 4; tt++) {
        float dv = 1.0f / fmaxf(dens[t0 + tt], 1e-6f);
        float o0 = acc[tt][0] * dv, o1 = acc[tt][1] * dv;
        float o2 = acc[tt][2] * dv, o3 = acc[tt][3] * dv;
        __half h0 = __float2half_rn(o0), h1 = __float2half_rn(o1);
        __half h2 = __float2half_rn(o2), h3 = __float2half_rn(o3);
        __half l0 = __float2half_rn(o0 - __half2float(h0));
        __half l1 = __float2half_rn(o1 - __half2float(h1));
        __half l2 = __float2half_rn(o2 - __half2float(h2));
        __half l3 = __float2half_rn(o3 - __half2float(h3));
        size_t base = ((size_t)(b * Sq + s0 + t0 + tt)) * Dq + h * HDq + e0;
        *(uint2*)(&g_oh[base]) = make_uint2(pack2h(h0, h1), pack2h(h2, h3));
        *(uint2*)(&g_ol[base]) = make_uint2(pack2h(l0, l1), pack2h(l2, l3));
    }
}

// ---------------- launch ----------------
extern "C" void kernel_launch(void* const* d_in, const int* in_sizes, int n_in,
                              void* d_out, int out_size) {
    const float* query = (const float*)d_in[0];
    const void*  maskraw = d_in[3];
    const float* Win  = (const float*)d_in[4];
    const float* bin  = (const float*)d_in[5];
    const float* Wout = (const float*)d_in[6];
    const float* bout = (const float*)d_in[7];
    float* out = (float*)d_out;

    static int attr_done = 0;
    if (!attr_done) {
        cudaFuncSetAttribute(tc_gemm, cudaFuncAttributeMaxDynamicSharedMemorySize, GEMM_SMEM);
        attr_done = 1;
    }

    setup_kernel<<<2048, 256>>>(maskraw, query, Win, Wout);            // 1

    dim3 g1(Nqkv / 128, Mq / 64);    // (12, 512)
    tc_gemm<<<g1, 128, GEMM_SMEM>>>(bin, nullptr, 0);                  // 2

    kv_kernel<<<dim3(Bq * Hq, KV_CHUNKS), 256>>>();                    // 3
    attn_kernel<<<dim3(Bq * Hq, Sq / 128), 512>>>();                   // 4 <- ncu slot

    dim3 g2(Dq / 128, Mq / 64);      // (4, 512)
    tc_gemm<<<g2, 128, GEMM_SMEM>>>(bout, out, 1);                     // 5
}

// round 16
// speedup vs baseline: 1.0723x; 1.0723x over previous
#include <cuda_runtime.h>
#include <cuda_bf16.h>
#include <cuda_fp16.h>
#include <math.h>
#include <stdint.h>

// Problem constants
#define Bq 4
#define Sq 8192
#define Dq 512
#define Hq 8
#define HDq 64
#define Mq (Bq * Sq)           // 32768
#define Nqkv (3 * Dq)          // 1536

// ---------------- scratch (static device memory; no allocations) ----------------
__device__ float g_q[(size_t)Mq * Dq];
__device__ float g_k[(size_t)Mq * Dq];
__device__ float g_v[(size_t)Mq * Dq];
__device__ float g_kv[Bq * Hq * HDq * HDq];
__device__ float g_ksum[Bq * Hq * HDq];
__device__ float g_mask[Mq];
// fp16 split operands: A = ah + al (2-term), B = bh only
__device__ __half g_ah[(size_t)Mq * Dq];     // query hi
__device__ __half g_al[(size_t)Mq * Dq];     // query lo
__device__ __half g_oh[(size_t)Mq * Dq];     // attn out hi
__device__ __half g_ol[(size_t)Mq * Dq];     // attn out lo
__device__ __half g_wih[(size_t)Nqkv * Dq];  // in_proj W (fp16)
__device__ __half g_woh[(size_t)Dq * Dq];    // out_proj W (fp16)

__device__ __forceinline__ uint32_t smem_u32(const void* p) {
    uint32_t a;
    asm("{ .reg .u64 t; cvta.to.shared.u64 t, %1; cvt.u32.u64 %0, t; }" : "=r"(a) : "l"(p));
    return a;
}

#define CP_ASYNC16(dst, src) \
    asm volatile("cp.async.cg.shared.global [%0], [%1], 16;" :: "r"(dst), "l"(src))
#define CP_COMMIT() asm volatile("cp.async.commit_group;" ::: "memory")
#define CP_WAIT(N)  asm volatile("cp.async.wait_group %0;" :: "n"(N) : "memory")

__device__ __forceinline__ float phi(float x) { return x > 0.0f ? x + 1.0f : expf(x); }

__device__ __forceinline__ uint32_t pack2h(__half a, __half b) {
    __half2 p; p.x = a; p.y = b;
    return *reinterpret_cast<uint32_t*>(&p);
}

// ---------------- fused setup: mask canonicalization + kv zero + fp16 splits ----------------
#define N4_Q   ((Mq * (size_t)Dq) / 4)
#define N4_WI  ((Nqkv * (size_t)Dq) / 4)
#define N4_WO  ((Dq * (size_t)Dq) / 4)
__global__ void setup_kernel(const void* __restrict__ mraw, const float* __restrict__ q,
                             const float* __restrict__ wi, const float* __restrict__ wo) {
    const size_t gtid = blockIdx.x * (size_t)blockDim.x + threadIdx.x;
    const size_t gstride = gridDim.x * (size_t)blockDim.x;

    if (blockIdx.x == 0) {
        __shared__ int s_f32, s_big;
        if (threadIdx.x == 0) { s_f32 = 0; s_big = 0; }
        __syncthreads();
        const unsigned int* w = (const unsigned int*)mraw;
        int f32 = 0, big = 0;
        for (int i = threadIdx.x; i < 8192; i += blockDim.x) {
            unsigned int x = w[i];
            if (x == 0x3F800000u) f32 = 1;
            else if (x > 1u) big = 1;
        }
        if (f32) atomicOr(&s_f32, 1);
        if (big) atomicOr(&s_big, 1);
        __syncthreads();
        int mode = s_f32 ? 2 : (s_big ? 0 : 1);
        for (int i = threadIdx.x; i < Mq; i += blockDim.x) {
            bool pad;
            if (mode == 0)      pad = ((const unsigned char*)mraw)[i] != 0;
            else if (mode == 1) pad = ((const int*)mraw)[i] != 0;
            else                pad = ((const float*)mraw)[i] != 0.0f;
            g_mask[i] = pad ? 0.0f : 1.0f;
        }
    }
    for (size_t i = gtid; i < Bq * Hq * HDq * HDq; i += gstride) g_kv[i] = 0.0f;
    for (size_t i = gtid; i < Bq * Hq * HDq; i += gstride) g_ksum[i] = 0.0f;

    const size_t total = N4_Q + N4_WI + N4_WO;
    for (size_t i = gtid; i < total; i += gstride) {
        const float* src; __half *dh, *dl; size_t j; bool wantlo;
        if (i < N4_Q)              { src = q;  dh = g_ah;  dl = g_al; j = i; wantlo = true; }
        else if (i < N4_Q + N4_WI) { src = wi; dh = g_wih; dl = 0; j = i - N4_Q; wantlo = false; }
        else                       { src = wo; dh = g_woh; dl = 0; j = i - N4_Q - N4_WI; wantlo = false; }
        float4 v = ((const float4*)src)[j];
        __half h0 = __float2half_rn(v.x), h1 = __float2half_rn(v.y);
        __half h2 = __float2half_rn(v.z), h3 = __float2half_rn(v.w);
        ((uint2*)dh)[j] = make_uint2(pack2h(h0, h1), pack2h(h2, h3));
        if (wantlo) {
            __half l0 = __float2half_rn(v.x - __half2float(h0));
            __half l1 = __float2half_rn(v.y - __half2float(h1));
            __half l2 = __float2half_rn(v.z - __half2float(h2));
            __half l3 = __float2half_rn(v.w - __half2float(h3));
            ((uint2*)dl)[j] = make_uint2(pack2h(l0, l1), pack2h(l2, l3));
        }
    }
}

#define LDM_X4(r0, r1, r2, r3, addr) \
    asm volatile("ldmatrix.sync.aligned.m8n8.x4.shared.b16 {%0,%1,%2,%3}, [%4];" \
                 : "=r"(r0), "=r"(r1), "=r"(r2), "=r"(r3) : "r"(addr))

__device__ __forceinline__ void mma_fp16(float* c, const uint32_t* a, uint32_t b0, uint32_t b1) {
    asm volatile(
        "mma.sync.aligned.m16n8k16.row.col.f32.f16.f16.f32 "
        "{%0,%1,%2,%3}, {%4,%5,%6,%7}, {%8,%9}, {%0,%1,%2,%3};"
        : "+f"(c[0]), "+f"(c[1]), "+f"(c[2]), "+f"(c[3])
        : "r"(a[0]), "r"(a[1]), "r"(a[2]), "r"(a[3]), "r"(b0), "r"(b1));
}

// ---------------- tensor-core GEMM (R12-proven): 128x128 CTA tile, 2 CTAs/SM ----------------
#define STG_STRIDE 48
#define A_TILE_B  6144
#define B_TILE_B  6144
#define OFF_AL    A_TILE_B
#define OFF_BH    (2 * A_TILE_B)
#define SUB_B     (3 * A_TILE_B)
#define STAGE_B   (2 * SUB_B)
#define GEMM_SMEM (2 * STAGE_B)         // 73728 per CTA -> 2 CTAs/SM
#define NCHUNK 16

__global__ __launch_bounds__(256, 2)
void tc_gemm(const float* __restrict__ bias, float* __restrict__ Cout, int mode) {
    extern __shared__ __align__(128) unsigned char smbuf[];

    const __half *Ah, *Al, *Bh;
    if (mode == 0) { Ah = g_ah; Al = g_al; Bh = g_wih; }
    else           { Ah = g_oh; Al = g_ol; Bh = g_woh; }

    const int tid = threadIdx.x;
    const int lane = tid & 31, warp = tid >> 5;
    const int wr = warp >> 2, wc = warp & 3;
    const int m0 = blockIdx.y * 128, n0 = blockIdx.x * 128;
    const uint32_t sb = smem_u32(smbuf);

    const int arow = tid >> 1;
    const int half = tid & 1;
    const __half* srcAh = Ah + (size_t)(m0 + arow) * Dq + half * 8;
    const __half* srcAl = Al + (size_t)(m0 + arow) * Dq + half * 8;
    const __half* srcBh = Bh + (size_t)(n0 + arow) * Dq + half * 8;
    const uint32_t dstA = sb + (uint32_t)(arow * STG_STRIDE + half * 16);
    const uint32_t dstB = dstA + OFF_BH;

    const int quad = lane >> 3, lrow = lane & 7;
    const uint32_t rowoff = (uint32_t)(((quad & 1) * 8 + lrow) * STG_STRIDE + (quad >> 1) * 16);

    float acc[4][4][4];
#pragma unroll
    for (int i = 0; i < 4; i++)
#pragma unroll
        for (int j = 0; j < 4; j++)
#pragma unroll
            for (int r = 0; r < 4; r++) acc[i][j][r] = 0.0f;

#pragma unroll
    for (int s = 0; s < 2; s++) {
        uint32_t so = (uint32_t)(s * SUB_B);
        CP_ASYNC16(dstA + so, srcAh + s * 16);
        CP_ASYNC16(dstA + so + OFF_AL, srcAl + s * 16);
        CP_ASYNC16(dstB + so, srcBh + s * 16);
    }
    CP_COMMIT();

#pragma unroll 2
    for (int c = 0; c < NCHUNK; c++) {
        if (c < NCHUNK - 1) {
            uint32_t ds = (uint32_t)(((c + 1) & 1) * STAGE_B);
#pragma unroll
            for (int s = 0; s < 2; s++) {
                uint32_t so = ds + (uint32_t)(s * SUB_B);
                int ko = (c + 1) * 32 + s * 16;
                CP_ASYNC16(dstA + so, srcAh + ko);
                CP_ASYNC16(dstA + so + OFF_AL, srcAl + ko);
                CP_ASYNC16(dstB + so, srcBh + ko);
            }
            CP_COMMIT();
            CP_WAIT(1);
        } else {
            CP_WAIT(0);
        }
        __syncthreads();

#pragma unroll
        for (int s = 0; s < 2; s++) {
            uint32_t stage = sb + (uint32_t)((c & 1) * STAGE_B) + (uint32_t)(s * SUB_B);
            uint32_t bh[2][4];
#pragma unroll
            for (int np = 0; np < 2; np++) {
                uint32_t baddr = stage + OFF_BH +
                                 (uint32_t)((wc * 32 + np * 16) * STG_STRIDE) + rowoff;
                LDM_X4(bh[np][0], bh[np][1], bh[np][2], bh[np][3], baddr);
            }
            uint32_t ah[4][4];
#pragma unroll
            for (int mf = 0; mf < 4; mf++) {
                uint32_t aaddr = stage + (uint32_t)((wr * 64 + mf * 16) * STG_STRIDE) + rowoff;
                LDM_X4(ah[mf][0], ah[mf][1], ah[mf][2], ah[mf][3], aaddr);
            }
#pragma unroll
            for (int mf = 0; mf < 4; mf++)
#pragma unroll
                for (int nf = 0; nf < 4; nf++) {
                    int np = nf >> 1, od = nf & 1;
                    mma_fp16(acc[mf][nf], ah[mf], bh[np][od], bh[np][od + 2]);
                }
            uint32_t al[4][4];
#pragma unroll
            for (int mf = 0; mf < 4; mf++) {
                uint32_t aaddr = stage + OFF_AL +
                                 (uint32_t)((wr * 64 + mf * 16) * STG_STRIDE) + rowoff;
                LDM_X4(al[mf][0], al[mf][1], al[mf][2], al[mf][3], aaddr);
            }
#pragma unroll
            for (int mf = 0; mf < 4; mf++)
#pragma unroll
                for (int nf = 0; nf < 4; nf++) {
                    int np = nf >> 1, od = nf & 1;
                    mma_fp16(acc[mf][nf], al[mf], bh[np][od], bh[np][od + 2]);
                }
        }
        __syncthreads();
    }

    // ---------------- epilogue ----------------
    int region = n0 >> 9;
    int nc0 = n0 & 511;
    float* dst = (mode == 1) ? Cout : (region == 0 ? g_q : (region == 1 ? g_k : g_v));

#pragma unroll
    for (int mf = 0; mf < 4; mf++) {
#pragma unroll
        for (int pr = 0; pr < 2; pr++) {
            int r = m0 + wr * 64 + mf * 16 + (lane >> 2) + pr * 8;
            float mv = (mode == 0) ? g_mask[r] : 0.0f;
#pragma unroll
            for (int nf = 0; nf < 4; nf++) {
                int col = wc * 32 + nf * 8 + (lane & 3) * 2;
                float2 bs = *(const float2*)(bias + n0 + col);
                float v0 = acc[mf][nf][pr * 2 + 0] + bs.x;
                float v1 = acc[mf][nf][pr * 2 + 1] + bs.y;
                if (mode == 0) {
                    if (region == 0)      { v0 = phi(v0);       v1 = phi(v1); }
                    else if (region == 1) { v0 = phi(v0) * mv;  v1 = phi(v1) * mv; }
                    else                  { v0 = v0 * mv;       v1 = v1 * mv; }
                    *(float2*)(dst + (size_t)r * Dq + nc0 + col) = make_float2(v0, v1);
                } else {
                    *(float2*)(dst + (size_t)r * Dq + n0 + col) = make_float2(v0, v1);
                }
            }
        }
    }
}

// ---------------- kv[bh][d][e] = sum_s k[s][d]*v[s][e]; ksum[bh][d] = sum_s k[s][d] ----------------
#define KV_CHUNKS 32
__global__ __launch_bounds__(256)
void kv_kernel() {
    const int bh = blockIdx.x;
    const int chunk = blockIdx.y;
    const int b = bh >> 3, h = bh & 7;
    const int CH = Sq / KV_CHUNKS;          // 256
    const int s_base = chunk * CH;
    const size_t tokbase = (size_t)b * Sq;

    __shared__ float ks[32][64];
    __shared__ float vs[32][64];

    const int tid = threadIdx.x;
    const int d0 = (tid >> 4) * 4;
    const int e0 = (tid & 15) * 4;
    const int lrow = tid >> 3;
    const int lcol = (tid & 7) * 8;

    float acc[4][4];
#pragma unroll
    for (int i = 0; i < 4; i++)
#pragma unroll
        for (int j = 0; j < 4; j++) acc[i][j] = 0.0f;
    float ksum[4] = {0.f, 0.f, 0.f, 0.f};

    for (int st = 0; st < CH; st += 32) {
        size_t gb = (tokbase + s_base + st + lrow) * Dq + h * HDq + lcol;
        float4 k1 = *(const float4*)(g_k + gb);
        float4 k2 = *(const float4*)(g_k + gb + 4);
        float4 v1 = *(const float4*)(g_v + gb);
        float4 v2 = *(const float4*)(g_v + gb + 4);
        *(float4*)&ks[lrow][lcol]     = k1;
        *(float4*)&ks[lrow][lcol + 4] = k2;
        *(float4*)&vs[lrow][lcol]     = v1;
        *(float4*)&vs[lrow][lcol + 4] = v2;
        __syncthreads();
#pragma unroll 8
        for (int s = 0; s < 32; s++) {
            float4 kd = *(const float4*)&ks[s][d0];
            float4 ve = *(const float4*)&vs[s][e0];
            float kdv[4] = {kd.x, kd.y, kd.z, kd.w};
            float vev[4] = {ve.x, ve.y, ve.z, ve.w};
#pragma unroll
            for (int i = 0; i < 4; i++)
#pragma unroll
                for (int j = 0; j < 4; j++) acc[i][j] = fmaf(kdv[i], vev[j], acc[i][j]);
            if (e0 == 0) {
#pragma unroll
                for (int i = 0; i < 4; i++) ksum[i] += kdv[i];
            }
        }
        __syncthreads();
    }

    float* kvp = g_kv + bh * (HDq * HDq);
#pragma unroll
    for (int i = 0; i < 4; i++)
#pragma unroll
        for (int j = 0; j < 4; j++)
            atomicAdd(&kvp[(d0 + i) * HDq + (e0 + j)], acc[i][j]);
    if (e0 == 0) {
#pragma unroll
        for (int i = 0; i < 4; i++) atomicAdd(&g_ksum[bh * HDq + d0 + i], ksum[i]);
    }
}

// ---------------- attn: 128-token tile, 256 threads, 4-token x 8-e blocking ----------------
// Thread (tq 0..31, te 0..7): tokens t0..t0+3, cols e0..e0+7.
// Per d: 2x LDS.128 (kv) + 4 scalar LDS (q) per 32 FMA -> 1.5 B/FMA (was 2.0),
// regs ~76 -> 3 CTAs/SM (37.5% occ).
__global__ __launch_bounds__(256, 3)
void attn_kernel() {
    const int bh = blockIdx.x;
    const int tile = blockIdx.y;
    const int b = bh >> 3, h = bh & 7;
    const int s0 = tile * 128;

    __shared__ float kvs[64][64];
    __shared__ float qs[128][64];
    __shared__ float ksm[64];
    __shared__ float dens[128];

    const int tid = threadIdx.x;

    {
        const float4* src = (const float4*)(g_kv + bh * (HDq * HDq));
        float4* dst = (float4*)&kvs[0][0];
        for (int i = tid; i < 1024; i += 256) dst[i] = src[i];
    }
    if (tid < 64) ksm[tid] = g_ksum[bh * HDq + tid];
    {
        // q tile: 128 rows x 64 cols = 2048 float4, 8 per thread, coalesced
        for (int i = tid; i < 2048; i += 256) {
            int row = i >> 4, col = (i & 15) * 4;
            *(float4*)&qs[row][col] =
                *(const float4*)(g_q + ((size_t)(b * Sq + s0 + row)) * Dq + h * HDq + col);
        }
    }
    __syncthreads();

    const int t0 = (tid >> 3) * 4;     // 0..124
    const int e0 = (tid & 7) * 8;      // 0..56
    float acc[4][8];
#pragma unroll
    for (int i = 0; i < 4; i++)
#pragma unroll
        for (int j = 0; j < 8; j++) acc[i][j] = 0.0f;
    float den[4] = {0.f, 0.f, 0.f, 0.f};

#pragma unroll 4
    for (int d = 0; d < 64; d++) {
        float4 k0 = *(const float4*)&kvs[d][e0];
        float4 k1 = *(const float4*)&kvs[d][e0 + 4];
        float kc = ksm[d];
#pragma unroll
        for (int tt = 0; tt < 4; tt++) {
            float qv = qs[t0 + tt][d];
            acc[tt][0] = fmaf(qv, k0.x, acc[tt][0]);
            acc[tt][1] = fmaf(qv, k0.y, acc[tt][1]);
            acc[tt][2] = fmaf(qv, k0.z, acc[tt][2]);
            acc[tt][3] = fmaf(qv, k0.w, acc[tt][3]);
            acc[tt][4] = fmaf(qv, k1.x, acc[tt][4]);
            acc[tt][5] = fmaf(qv, k1.y, acc[tt][5]);
            acc[tt][6] = fmaf(qv, k1.z, acc[tt][6]);
            acc[tt][7] = fmaf(qv, k1.w, acc[tt][7]);
            if (e0 == 0) den[tt] = fmaf(qv, kc, den[tt]);
        }
    }
    if (e0 == 0) {
#pragma unroll
        for (int tt = 0; tt < 4; tt++) dens[t0 + tt] = den[tt];
    }
    __syncthreads();

#pragma unroll
    for (int tt = 0; tt < 4; tt++) {
        float dv = 1.0f / fmaxf(dens[t0 + tt], 1e-6f);
        __half hx[8], lx[8];
#pragma unroll
        for (int j = 0; j < 8; j++) {
            float o = acc[tt][j] * dv;
            hx[j] = __float2half_rn(o);
            lx[j] = __float2half_rn(o - __half2float(hx[j]));
        }
        size_t base = ((size_t)(b * Sq + s0 + t0 + tt)) * Dq + h * HDq + e0;
        *(uint4*)(&g_oh[base]) = make_uint4(pack2h(hx[0], hx[1]), pack2h(hx[2], hx[3]),
                                            pack2h(hx[4], hx[5]), pack2h(hx[6], hx[7]));
        *(uint4*)(&g_ol[base]) = make_uint4(pack2h(lx[0], lx[1]), pack2h(lx[2], lx[3]),
                                            pack2h(lx[4], lx[5]), pack2h(lx[6], lx[7]));
    }
}

// ---------------- launch ----------------
extern "C" void kernel_launch(void* const* d_in, const int* in_sizes, int n_in,
                              void* d_out, int out_size) {
    const float* query = (const float*)d_in[0];
    const void*  maskraw = d_in[3];
    const float* Win  = (const float*)d_in[4];
    const float* bin  = (const float*)d_in[5];
    const float* Wout = (const float*)d_in[6];
    const float* bout = (const float*)d_in[7];
    float* out = (float*)d_out;

    static int attr_done = 0;
    if (!attr_done) {
        cudaFuncSetAttribute(tc_gemm, cudaFuncAttributeMaxDynamicSharedMemorySize, GEMM_SMEM);
        attr_done = 1;
    }

    setup_kernel<<<2048, 256>>>(maskraw, query, Win, Wout);            // 1

    dim3 g1(Nqkv / 128, Mq / 128);   // (12, 256)
    tc_gemm<<<g1, 256, GEMM_SMEM>>>(bin, nullptr, 0);                  // 2

    kv_kernel<<<dim3(Bq * Hq, KV_CHUNKS), 256>>>();                    // 3
    attn_kernel<<<dim3(Bq * Hq, Sq / 128), 256>>>();                   // 4 <- ncu slot

    dim3 g2(Dq / 128, Mq / 128);     // (4, 256)
    tc_gemm<<<g2, 256, GEMM_SMEM>>>(bout, out, 1);                     // 5
}

// round 17
// speedup vs baseline: 1.1793x; 1.0997x over previous
#include <cuda_runtime.h>
#include <cuda_bf16.h>
#include <cuda_fp16.h>
#include <math.h>
#include <stdint.h>

// Problem constants
#define Bq 4
#define Sq 8192
#define Dq 512
#define Hq 8
#define HDq 64
#define Mq (Bq * Sq)           // 32768
#define Nqkv (3 * Dq)          // 1536

// ---------------- scratch (static device memory; no allocations) ----------------
__device__ float g_q[(size_t)Mq * Dq];
__device__ float g_k[(size_t)Mq * Dq];
__device__ float g_v[(size_t)Mq * Dq];
__device__ float g_kv[Bq * Hq * HDq * HDq];
__device__ float g_ksum[Bq * Hq * HDq];
__device__ float g_mask[Mq];
// fp16 split operands
__device__ __half g_ah[(size_t)Mq * Dq];     // query hi
__device__ __half g_al[(size_t)Mq * Dq];     // query lo
__device__ __half g_oh[(size_t)Mq * Dq];     // attn out (fp16, single product in out-proj)
__device__ __half g_wih[(size_t)Nqkv * Dq];  // in_proj W (fp16)
__device__ __half g_woh[(size_t)Dq * Dq];    // out_proj W (fp16)

__device__ __forceinline__ uint32_t smem_u32(const void* p) {
    uint32_t a;
    asm("{ .reg .u64 t; cvta.to.shared.u64 t, %1; cvt.u32.u64 %0, t; }" : "=r"(a) : "l"(p));
    return a;
}

#define CP_ASYNC16(dst, src) \
    asm volatile("cp.async.cg.shared.global [%0], [%1], 16;" :: "r"(dst), "l"(src))
#define CP_COMMIT() asm volatile("cp.async.commit_group;" ::: "memory")
#define CP_WAIT(N)  asm volatile("cp.async.wait_group %0;" :: "n"(N) : "memory")

__device__ __forceinline__ float phi(float x) { return x > 0.0f ? x + 1.0f : expf(x); }

__device__ __forceinline__ uint32_t pack2h(__half a, __half b) {
    __half2 p; p.x = a; p.y = b;
    return *reinterpret_cast<uint32_t*>(&p);
}

// ---------------- fused setup: mask canonicalization + kv zero + fp16 splits ----------------
#define N4_Q   ((Mq * (size_t)Dq) / 4)
#define N4_WI  ((Nqkv * (size_t)Dq) / 4)
#define N4_WO  ((Dq * (size_t)Dq) / 4)
__global__ void setup_kernel(const void* __restrict__ mraw, const float* __restrict__ q,
                             const float* __restrict__ wi, const float* __restrict__ wo) {
    const size_t gtid = blockIdx.x * (size_t)blockDim.x + threadIdx.x;
    const size_t gstride = gridDim.x * (size_t)blockDim.x;

    if (blockIdx.x == 0) {
        __shared__ int s_f32, s_big;
        if (threadIdx.x == 0) { s_f32 = 0; s_big = 0; }
        __syncthreads();
        const unsigned int* w = (const unsigned int*)mraw;
        int f32 = 0, big = 0;
        for (int i = threadIdx.x; i < 8192; i += blockDim.x) {
            unsigned int x = w[i];
            if (x == 0x3F800000u) f32 = 1;
            else if (x > 1u) big = 1;
        }
        if (f32) atomicOr(&s_f32, 1);
        if (big) atomicOr(&s_big, 1);
        __syncthreads();
        int mode = s_f32 ? 2 : (s_big ? 0 : 1);
        for (int i = threadIdx.x; i < Mq; i += blockDim.x) {
            bool pad;
            if (mode == 0)      pad = ((const unsigned char*)mraw)[i] != 0;
            else if (mode == 1) pad = ((const int*)mraw)[i] != 0;
            else                pad = ((const float*)mraw)[i] != 0.0f;
            g_mask[i] = pad ? 0.0f : 1.0f;
        }
    }
    for (size_t i = gtid; i < Bq * Hq * HDq * HDq; i += gstride) g_kv[i] = 0.0f;
    for (size_t i = gtid; i < Bq * Hq * HDq; i += gstride) g_ksum[i] = 0.0f;

    const size_t total = N4_Q + N4_WI + N4_WO;
    for (size_t i = gtid; i < total; i += gstride) {
        const float* src; __half *dh, *dl; size_t j; bool wantlo;
        if (i < N4_Q)              { src = q;  dh = g_ah;  dl = g_al; j = i; wantlo = true; }
        else if (i < N4_Q + N4_WI) { src = wi; dh = g_wih; dl = 0; j = i - N4_Q; wantlo = false; }
        else                       { src = wo; dh = g_woh; dl = 0; j = i - N4_Q - N4_WI; wantlo = false; }
        float4 v = ((const float4*)src)[j];
        __half h0 = __float2half_rn(v.x), h1 = __float2half_rn(v.y);
        __half h2 = __float2half_rn(v.z), h3 = __float2half_rn(v.w);
        ((uint2*)dh)[j] = make_uint2(pack2h(h0, h1), pack2h(h2, h3));
        if (wantlo) {
            __half l0 = __float2half_rn(v.x - __half2float(h0));
            __half l1 = __float2half_rn(v.y - __half2float(h1));
            __half l2 = __float2half_rn(v.z - __half2float(h2));
            __half l3 = __float2half_rn(v.w - __half2float(h3));
            ((uint2*)dl)[j] = make_uint2(pack2h(l0, l1), pack2h(l2, l3));
        }
    }
}

#define LDM_X4(r0, r1, r2, r3, addr) \
    asm volatile("ldmatrix.sync.aligned.m8n8.x4.shared.b16 {%0,%1,%2,%3}, [%4];" \
                 : "=r"(r0), "=r"(r1), "=r"(r2), "=r"(r3) : "r"(addr))

__device__ __forceinline__ void mma_fp16(float* c, const uint32_t* a, uint32_t b0, uint32_t b1) {
    asm volatile(
        "mma.sync.aligned.m16n8k16.row.col.f32.f16.f16.f32 "
        "{%0,%1,%2,%3}, {%4,%5,%6,%7}, {%8,%9}, {%0,%1,%2,%3};"
        : "+f"(c[0]), "+f"(c[1]), "+f"(c[2]), "+f"(c[3])
        : "r"(a[0]), "r"(a[1]), "r"(a[2]), "r"(a[3]), "r"(b0), "r"(b1));
}

// ---------------- tensor-core GEMM (R12 config): 128x128 CTA tile, 2 CTAs/SM ----------------
// MODE 0: A=(g_ah,g_al) 2-product, B=g_wih, QKV epilogue -> g_q/g_k/g_v
// MODE 1: A=g_oh single product, B=g_woh, plain epilogue -> Cout (half the MMAs)
#define STG_STRIDE 48
#define A_TILE_B  6144
#define B_TILE_B  6144
#define OFF_AL    A_TILE_B
#define OFF_BH    (2 * A_TILE_B)
#define SUB_B     (3 * A_TILE_B)
#define STAGE_B   (2 * SUB_B)
#define GEMM_SMEM (2 * STAGE_B)         // 73728 per CTA -> 2 CTAs/SM
#define NCHUNK 16

template <int MODE>
__global__ __launch_bounds__(256, 2)
void tc_gemm(const float* __restrict__ bias, float* __restrict__ Cout) {
    extern __shared__ __align__(128) unsigned char smbuf[];

    const __half* Ah = (MODE == 0) ? g_ah : g_oh;
    const __half* Al = g_al;                        // used only when MODE==0
    const __half* Bh = (MODE == 0) ? g_wih : g_woh;

    const int tid = threadIdx.x;
    const int lane = tid & 31, warp = tid >> 5;
    const int wr = warp >> 2, wc = warp & 3;
    const int m0 = blockIdx.y * 128, n0 = blockIdx.x * 128;
    const uint32_t sb = smem_u32(smbuf);

    const int arow = tid >> 1;
    const int half = tid & 1;
    const __half* srcAh = Ah + (size_t)(m0 + arow) * Dq + half * 8;
    const __half* srcAl = Al + (size_t)(m0 + arow) * Dq + half * 8;
    const __half* srcBh = Bh + (size_t)(n0 + arow) * Dq + half * 8;
    const uint32_t dstA = sb + (uint32_t)(arow * STG_STRIDE + half * 16);
    const uint32_t dstB = dstA + OFF_BH;

    const int quad = lane >> 3, lrow = lane & 7;
    const uint32_t rowoff = (uint32_t)(((quad & 1) * 8 + lrow) * STG_STRIDE + (quad >> 1) * 16);

    float acc[4][4][4];
#pragma unroll
    for (int i = 0; i < 4; i++)
#pragma unroll
        for (int j = 0; j < 4; j++)
#pragma unroll
            for (int r = 0; r < 4; r++) acc[i][j][r] = 0.0f;

#pragma unroll
    for (int s = 0; s < 2; s++) {
        uint32_t so = (uint32_t)(s * SUB_B);
        CP_ASYNC16(dstA + so, srcAh + s * 16);
        if (MODE == 0) CP_ASYNC16(dstA + so + OFF_AL, srcAl + s * 16);
        CP_ASYNC16(dstB + so, srcBh + s * 16);
    }
    CP_COMMIT();

#pragma unroll 2
    for (int c = 0; c < NCHUNK; c++) {
        if (c < NCHUNK - 1) {
            uint32_t ds = (uint32_t)(((c + 1) & 1) * STAGE_B);
#pragma unroll
            for (int s = 0; s < 2; s++) {
                uint32_t so = ds + (uint32_t)(s * SUB_B);
                int ko = (c + 1) * 32 + s * 16;
                CP_ASYNC16(dstA + so, srcAh + ko);
                if (MODE == 0) CP_ASYNC16(dstA + so + OFF_AL, srcAl + ko);
                CP_ASYNC16(dstB + so, srcBh + ko);
            }
            CP_COMMIT();
            CP_WAIT(1);
        } else {
            CP_WAIT(0);
        }
        __syncthreads();

#pragma unroll
        for (int s = 0; s < 2; s++) {
            uint32_t stage = sb + (uint32_t)((c & 1) * STAGE_B) + (uint32_t)(s * SUB_B);
            uint32_t bh[2][4];
#pragma unroll
            for (int np = 0; np < 2; np++) {
                uint32_t baddr = stage + OFF_BH +
                                 (uint32_t)((wc * 32 + np * 16) * STG_STRIDE) + rowoff;
                LDM_X4(bh[np][0], bh[np][1], bh[np][2], bh[np][3], baddr);
            }
            uint32_t ah[4][4];
#pragma unroll
            for (int mf = 0; mf < 4; mf++) {
                uint32_t aaddr = stage + (uint32_t)((wr * 64 + mf * 16) * STG_STRIDE) + rowoff;
                LDM_X4(ah[mf][0], ah[mf][1], ah[mf][2], ah[mf][3], aaddr);
            }
            // P1: ah*bh
#pragma unroll
            for (int mf = 0; mf < 4; mf++)
#pragma unroll
                for (int nf = 0; nf < 4; nf++) {
                    int np = nf >> 1, od = nf & 1;
                    mma_fp16(acc[mf][nf], ah[mf], bh[np][od], bh[np][od + 2]);
                }
            if (MODE == 0) {
                uint32_t al[4][4];
#pragma unroll
                for (int mf = 0; mf < 4; mf++) {
                    uint32_t aaddr = stage + OFF_AL +
                                     (uint32_t)((wr * 64 + mf * 16) * STG_STRIDE) + rowoff;
                    LDM_X4(al[mf][0], al[mf][1], al[mf][2], al[mf][3], aaddr);
                }
                // P2: al*bh
#pragma unroll
                for (int mf = 0; mf < 4; mf++)
#pragma unroll
                    for (int nf = 0; nf < 4; nf++) {
                        int np = nf >> 1, od = nf & 1;
                        mma_fp16(acc[mf][nf], al[mf], bh[np][od], bh[np][od + 2]);
                    }
            }
        }
        __syncthreads();
    }

    // ---------------- epilogue ----------------
    int region = n0 >> 9;
    int nc0 = n0 & 511;
    float* dst = (MODE == 1) ? Cout : (region == 0 ? g_q : (region == 1 ? g_k : g_v));

#pragma unroll
    for (int mf = 0; mf < 4; mf++) {
#pragma unroll
        for (int pr = 0; pr < 2; pr++) {
            int r = m0 + wr * 64 + mf * 16 + (lane >> 2) + pr * 8;
            float mv = (MODE == 0) ? g_mask[r] : 0.0f;
#pragma unroll
            for (int nf = 0; nf < 4; nf++) {
                int col = wc * 32 + nf * 8 + (lane & 3) * 2;
                float2 bs = *(const float2*)(bias + n0 + col);
                float v0 = acc[mf][nf][pr * 2 + 0] + bs.x;
                float v1 = acc[mf][nf][pr * 2 + 1] + bs.y;
                if (MODE == 0) {
                    if (region == 0)      { v0 = phi(v0);       v1 = phi(v1); }
                    else if (region == 1) { v0 = phi(v0) * mv;  v1 = phi(v1) * mv; }
                    else                  { v0 = v0 * mv;       v1 = v1 * mv; }
                    *(float2*)(dst + (size_t)r * Dq + nc0 + col) = make_float2(v0, v1);
                } else {
                    *(float2*)(dst + (size_t)r * Dq + n0 + col) = make_float2(v0, v1);
                }
            }
        }
    }
}

// ---------------- kv[bh][d][e] = sum_s k[s][d]*v[s][e]; ksum[bh][d] = sum_s k[s][d] ----------------
#define KV_CHUNKS 32
__global__ __launch_bounds__(256)
void kv_kernel() {
    const int bh = blockIdx.x;
    const int chunk = blockIdx.y;
    const int b = bh >> 3, h = bh & 7;
    const int CH = Sq / KV_CHUNKS;          // 256
    const int s_base = chunk * CH;
    const size_t tokbase = (size_t)b * Sq;

    __shared__ float ks[32][64];
    __shared__ float vs[32][64];

    const int tid = threadIdx.x;
    const int d0 = (tid >> 4) * 4;
    const int e0 = (tid & 15) * 4;
    const int lrow = tid >> 3;
    const int lcol = (tid & 7) * 8;

    float acc[4][4];
#pragma unroll
    for (int i = 0; i < 4; i++)
#pragma unroll
        for (int j = 0; j < 4; j++) acc[i][j] = 0.0f;
    float ksum[4] = {0.f, 0.f, 0.f, 0.f};

    for (int st = 0; st < CH; st += 32) {
        size_t gb = (tokbase + s_base + st + lrow) * Dq + h * HDq + lcol;
        float4 k1 = *(const float4*)(g_k + gb);
        float4 k2 = *(const float4*)(g_k + gb + 4);
        float4 v1 = *(const float4*)(g_v + gb);
        float4 v2 = *(const float4*)(g_v + gb + 4);
        *(float4*)&ks[lrow][lcol]     = k1;
        *(float4*)&ks[lrow][lcol + 4] = k2;
        *(float4*)&vs[lrow][lcol]     = v1;
        *(float4*)&vs[lrow][lcol + 4] = v2;
        __syncthreads();
#pragma unroll 8
        for (int s = 0; s < 32; s++) {
            float4 kd = *(const float4*)&ks[s][d0];
            float4 ve = *(const float4*)&vs[s][e0];
            float kdv[4] = {kd.x, kd.y, kd.z, kd.w};
            float vev[4] = {ve.x, ve.y, ve.z, ve.w};
#pragma unroll
            for (int i = 0; i < 4; i++)
#pragma unroll
                for (int j = 0; j < 4; j++) acc[i][j] = fmaf(kdv[i], vev[j], acc[i][j]);
            if (e0 == 0) {
#pragma unroll
                for (int i = 0; i < 4; i++) ksum[i] += kdv[i];
            }
        }
        __syncthreads();
    }

    float* kvp = g_kv + bh * (HDq * HDq);
#pragma unroll
    for (int i = 0; i < 4; i++)
#pragma unroll
        for (int j = 0; j < 4; j++)
            atomicAdd(&kvp[(d0 + i) * HDq + (e0 + j)], acc[i][j]);
    if (e0 == 0) {
#pragma unroll
        for (int i = 0; i < 4; i++) atomicAdd(&g_ksum[bh * HDq + d0 + i], ksum[i]);
    }
}

// ---------------- attn (R12-proven blocking): 128-token tiles, 512 threads ----------------
// Writes fp16 hi only (out-proj is single-product on A).
__global__ __launch_bounds__(512)
void attn_kernel() {
    const int bh = blockIdx.x;
    const int tile = blockIdx.y;
    const int b = bh >> 3, h = bh & 7;
    const int s0 = tile * 128;

    __shared__ float kvs[64][64];
    __shared__ float qs[128][64];
    __shared__ float ksm[64];
    __shared__ float dens[128];

    const int tid = threadIdx.x;

    {
        const float4* src = (const float4*)(g_kv + bh * (HDq * HDq));
        float4* dst = (float4*)&kvs[0][0];
        for (int i = tid; i < 1024; i += 512) dst[i] = src[i];
    }
    if (tid < 64) ksm[tid] = g_ksum[bh * HDq + tid];
    {
        int t = tid >> 2;
        int off = (tid & 3) * 16;
        const float4* src = (const float4*)(g_q + ((size_t)(b * Sq + s0 + t)) * Dq + h * HDq + off);
        float4* dst = (float4*)&qs[t][off];
#pragma unroll
        for (int u = 0; u < 4; u++) dst[u] = src[u];
    }
    __syncthreads();

    const int t0 = (tid >> 4) * 4;
    const int e0 = (tid & 15) * 4;
    float acc[4][4];
#pragma unroll
    for (int i = 0; i < 4; i++)
#pragma unroll
        for (int j = 0; j < 4; j++) acc[i][j] = 0.0f;
    float den[4] = {0.f, 0.f, 0.f, 0.f};

#pragma unroll 8
    for (int d = 0; d < 64; d++) {
        float4 kv4 = *(const float4*)&kvs[d][e0];
        float kvv[4] = {kv4.x, kv4.y, kv4.z, kv4.w};
        float kc = ksm[d];
#pragma unroll
        for (int tt = 0; tt < 4; tt++) {
            float qv = qs[t0 + tt][d];
#pragma unroll
            for (int j = 0; j < 4; j++) acc[tt][j] = fmaf(qv, kvv[j], acc[tt][j]);
            if (e0 == 0) den[tt] = fmaf(qv, kc, den[tt]);
        }
    }
    if (e0 == 0) {
#pragma unroll
        for (int tt = 0; tt < 4; tt++) dens[t0 + tt] = den[tt];
    }
    __syncthreads();

#pragma unroll
    for (int tt = 0; tt < 4; tt++) {
        float dv = 1.0f / fmaxf(dens[t0 + tt], 1e-6f);
        float o0 = acc[tt][0] * dv, o1 = acc[tt][1] * dv;
        float o2 = acc[tt][2] * dv, o3 = acc[tt][3] * dv;
        __half h0 = __float2half_rn(o0), h1 = __float2half_rn(o1);
        __half h2 = __float2half_rn(o2), h3 = __float2half_rn(o3);
        size_t base = ((size_t)(b * Sq + s0 + t0 + tt)) * Dq + h * HDq + e0;
        *(uint2*)(&g_oh[base]) = make_uint2(pack2h(h0, h1), pack2h(h2, h3));
    }
}

// ---------------- launch ----------------
extern "C" void kernel_launch(void* const* d_in, const int* in_sizes, int n_in,
                              void* d_out, int out_size) {
    const float* query = (const float*)d_in[0];
    const void*  maskraw = d_in[3];
    const float* Win  = (const float*)d_in[4];
    const float* bin  = (const float*)d_in[5];
    const float* Wout = (const float*)d_in[6];
    const float* bout = (const float*)d_in[7];
    float* out = (float*)d_out;

    static int attr_done = 0;
    if (!attr_done) {
        cudaFuncSetAttribute(tc_gemm<0>, cudaFuncAttributeMaxDynamicSharedMemorySize, GEMM_SMEM);
        cudaFuncSetAttribute(tc_gemm<1>, cudaFuncAttributeMaxDynamicSharedMemorySize, GEMM_SMEM);
        attr_done = 1;
    }

    setup_kernel<<<2048, 256>>>(maskraw, query, Win, Wout);            // 1

    dim3 g1(Nqkv / 128, Mq / 128);   // (12, 256)
    tc_gemm<0><<<g1, 256, GEMM_SMEM>>>(bin, nullptr);                  // 2

    kv_kernel<<<dim3(Bq * Hq, KV_CHUNKS), 256>>>();                    // 3
    attn_kernel<<<dim3(Bq * Hq, Sq / 128), 512>>>();                   // 4 <- ncu slot

    dim3 g2(Dq / 128, Mq / 128);     // (4, 256)
    tc_gemm<1><<<g2, 256, GEMM_SMEM>>>(bout, out);                     // 5
}